// round 6
// baseline (speedup 1.0000x reference)
#include <cuda_runtime.h>
#include <math.h>
#include <stddef.h>
#include <stdint.h>

// ---------------- problem constants ----------------
#define TOKS   8192
#define CDIM   768
#define HID    384
#define NHEAD  12
#define HDIM   64
#define SEQ    1024
#define QKVC   2304
#define NBH    96

// ---------------- scratch ---------------------------
__device__ float g_h[(size_t)TOKS * CDIM];
__device__ float g_qkv[(size_t)TOKS * QKVC];
__device__ float g_att[(size_t)TOKS * CDIM];
__device__ float g_x1[(size_t)TOKS * CDIM];
__device__ float g_fc1[(size_t)TOKS * HID];
__device__ float g_wqkv_t[(size_t)QKVC * CDIM];
__device__ float g_wproj_t[(size_t)CDIM * CDIM];
__device__ float g_wfc1_t[(size_t)HID * CDIM];
__device__ float g_wfc2_t[(size_t)CDIM * HID];

typedef unsigned long long u64;

// ---------------- helpers -----------------------
__device__ __forceinline__ uint32_t smem_u32(const void* p) {
    uint32_t a;
    asm("{ .reg .u64 t; cvta.to.shared.u64 t, %1; cvt.u32.u64 %0, t; }" : "=r"(a) : "l"(p));
    return a;
}
__device__ __forceinline__ void cp_async16(uint32_t dst, const void* src) {
    asm volatile("cp.async.cg.shared.global [%0], [%1], 16;" :: "r"(dst), "l"(src));
}
#define CP_COMMIT() asm volatile("cp.async.commit_group;" ::: "memory")
#define SWZ(b) ((b) ^ (((b) >> 3) & 0x70))

__device__ __forceinline__ uint32_t lds32(uint32_t a) {
    uint32_t v;
    asm volatile("ld.shared.b32 %0, [%1];" : "=r"(v) : "r"(a));
    return v;
}

__device__ __forceinline__ void mma_tf32(float* d, const uint32_t* a, const uint32_t* b) {
    asm volatile(
        "mma.sync.aligned.m16n8k8.row.col.f32.tf32.tf32.f32 "
        "{%0,%1,%2,%3}, {%4,%5,%6,%7}, {%8,%9}, {%0,%1,%2,%3};"
        : "+f"(d[0]), "+f"(d[1]), "+f"(d[2]), "+f"(d[3])
        : "r"(a[0]), "r"(a[1]), "r"(a[2]), "r"(a[3]), "r"(b[0]), "r"(b[1]));
}

__device__ __forceinline__ float cvt_tf32(float x) {
    uint32_t u;
    asm("cvt.rna.tf32.f32 %0, %1;" : "=r"(u) : "f"(x));
    return __uint_as_float(u);
}

// ---------------- weight transpose: out[n,k] = in[k,n] -------------------
__global__ void transpose_kernel(const float* __restrict__ in, float* __restrict__ out,
                                 int K, int N) {
    __shared__ float t[32][33];
    int bn = blockIdx.x << 5, bk = blockIdx.y << 5;
    int tx = threadIdx.x, ty = threadIdx.y;   // 32 x 8
#pragma unroll
    for (int i = 0; i < 4; i++)
        t[ty + i * 8][tx] = in[(size_t)(bk + ty + i * 8) * N + bn + tx];
    __syncthreads();
#pragma unroll
    for (int i = 0; i < 4; i++)
        out[(size_t)(bn + ty + i * 8) * K + bk + tx] = t[tx][ty + i * 8];
}

// ---------------- LayerNorm -------------------------------------------
__global__ void ln_kernel(const float* __restrict__ x, const float* __restrict__ w,
                          const float* __restrict__ b, float* __restrict__ out) {
    int row = blockIdx.x;
    const float* xr = x + (size_t)row * CDIM;
    float* orow = out + (size_t)row * CDIM;
    int t = threadIdx.x;
    float v0 = xr[t], v1 = xr[t + 256], v2 = xr[t + 512];
    float s = v0 + v1 + v2;
    float q = v0 * v0 + v1 * v1 + v2 * v2;
#pragma unroll
    for (int o = 16; o; o >>= 1) {
        s += __shfl_xor_sync(0xffffffffu, s, o);
        q += __shfl_xor_sync(0xffffffffu, q, o);
    }
    __shared__ float rs[8], rq[8];
    if ((t & 31) == 0) { rs[t >> 5] = s; rq[t >> 5] = q; }
    __syncthreads();
    if (t < 32) {
        float us = (t < 8) ? rs[t] : 0.f;
        float uq = (t < 8) ? rq[t] : 0.f;
#pragma unroll
        for (int o = 4; o; o >>= 1) {
            us += __shfl_xor_sync(0xffffffffu, us, o);
            uq += __shfl_xor_sync(0xffffffffu, uq, o);
        }
        if (t == 0) { rs[0] = us; rq[0] = uq; }
    }
    __syncthreads();
    float mu  = rs[0] * (1.f / CDIM);
    float var = rq[0] * (1.f / CDIM) - mu * mu;
    float inv = rsqrtf(var + 1e-5f);
    orow[t]       = (v0 - mu) * inv * w[t]       + b[t];
    orow[t + 256] = (v1 - mu) * inv * w[t + 256] + b[t + 256];
    orow[t + 512] = (v2 - mu) * inv * w[t + 512] + b[t + 512];
}

// ---------------- tf32 mma.sync GEMM, 3-stage cp.async pipeline ----------
// C[M,N] = A[M,K] @ Bt[N,K]^T. Tile 128x128, BK=32, 8 warps of 64x32.
// Prefetch distance 2; ONE __syncthreads per BK iteration.
#define STG 32768u
__global__ void __launch_bounds__(256)
gemm_mma(const float* __restrict__ A, const float* __restrict__ Bt,
         float* __restrict__ C, int N, int K,
         const float* __restrict__ bias, const float* __restrict__ resid,
         int gelu_flag) {
    extern __shared__ char smem[];
    const uint32_t sb = smem_u32(smem);
    const int tid = threadIdx.x;
    const int wid = tid >> 5, lane = tid & 31;
    const int warp_m = wid & 1, warp_n = wid >> 1;
    const int cl = lane & 3;
    const int r  = lane >> 2;
    const int bn = blockIdx.x << 7, bm = blockIdx.y << 7;

    const int nBK = K >> 5;

    float d[4][4][4];
#pragma unroll
    for (int i = 0; i < 4; i++)
#pragma unroll
        for (int j = 0; j < 4; j++)
#pragma unroll
            for (int e = 0; e < 4; e++) d[i][j][e] = 0.f;

#define LOADT(k0, stg)                                                          \
    {                                                                           \
        uint32_t base = sb + (uint32_t)(stg) * STG;                             \
        _Pragma("unroll")                                                       \
        for (int i = 0; i < 4; i++) {                                           \
            int id = tid + (i << 8);                                            \
            int row = id >> 3, c4 = id & 7;                                     \
            uint32_t byo = (uint32_t)(row * 128 + (c4 << 4));                   \
            uint32_t dst = base + SWZ(byo);                                     \
            cp_async16(dst, A + (size_t)(bm + row) * K + (k0) + (c4 << 2));     \
            cp_async16(dst + 16384u,                                            \
                       Bt + (size_t)(bn + row) * K + (k0) + (c4 << 2));         \
        }                                                                       \
        CP_COMMIT();                                                            \
    }

    LOADT(0, 0);
    LOADT(32, 1);

    const uint32_t swz16 = (uint32_t)r << 4;
    const uint32_t rowa = (uint32_t)(warp_m * 64 + r) * 128u;
    const uint32_t rowb = (uint32_t)(warp_n * 32 + r) * 128u;

    int stage = 0;
    for (int c = 0; c < nBK; c++) {
        if (c == nBK - 1) asm volatile("cp.async.wait_group 0;" ::: "memory");
        else              asm volatile("cp.async.wait_group 1;" ::: "memory");
        __syncthreads();

        // prefetch stage c+2 into buffer last consumed at iter c-1 (safe
        // after the barrier above)
        if (c + 2 < nBK) {
            int ns = stage + 2; if (ns >= 3) ns -= 3;
            LOADT((c + 2) << 5, ns);
        }

        const uint32_t Ab = sb + (uint32_t)stage * STG + rowa;
        const uint32_t Bb = sb + (uint32_t)stage * STG + 16384u + rowb;

#pragma unroll
        for (int ks = 0; ks < 4; ks++) {
            uint32_t k0x = (uint32_t)((ks * 8 + cl) << 2) ^ swz16;
            uint32_t k1x = (uint32_t)((ks * 8 + cl + 4) << 2) ^ swz16;
            uint32_t av[4][4], bv[4][2];
#pragma unroll
            for (int i = 0; i < 4; i++) {
                uint32_t r0 = Ab + (uint32_t)(i * 16 * 128);
                av[i][0] = lds32(r0 + k0x);
                av[i][1] = lds32(r0 + 8 * 128 + k0x);
                av[i][2] = lds32(r0 + k1x);
                av[i][3] = lds32(r0 + 8 * 128 + k1x);
            }
#pragma unroll
            for (int j = 0; j < 4; j++) {
                uint32_t rb = Bb + (uint32_t)(j * 8 * 128);
                bv[j][0] = lds32(rb + k0x);
                bv[j][1] = lds32(rb + k1x);
            }
#pragma unroll
            for (int i = 0; i < 4; i++)
#pragma unroll
                for (int j = 0; j < 4; j++) mma_tf32(d[i][j], av[i], bv[j]);
        }
        stage++; if (stage == 3) stage = 0;
    }

    const int m0w = bm + warp_m * 64 + r;
    const int n0w = bn + warp_n * 32 + cl * 2;
#pragma unroll
    for (int i = 0; i < 4; i++) {
#pragma unroll
        for (int h = 0; h < 2; h++) {
            int row = m0w + i * 16 + h * 8;
            float* Crow = C + (size_t)row * N;
            const float* Rrow = resid ? resid + (size_t)row * N : (const float*)0;
#pragma unroll
            for (int j = 0; j < 4; j++) {
                int col = n0w + j * 8;
                float v0 = d[i][j][h * 2 + 0];
                float v1 = d[i][j][h * 2 + 1];
                if (bias) { v0 += bias[col]; v1 += bias[col + 1]; }
                if (gelu_flag) {
                    v0 = 0.5f * v0 * (1.f + erff(v0 * 0.70710678118654752f));
                    v1 = 0.5f * v1 * (1.f + erff(v1 * 0.70710678118654752f));
                }
                if (Rrow) { v0 += Rrow[col]; v1 += Rrow[col + 1]; }
                *(float2*)&Crow[col] = make_float2(v0, v1);
            }
        }
    }
#undef LOADT
}
#define GEMM_SMEM (3 * 32768)

// ---------------- flash attention, tensor-core version --------------------
#define FD 68

__global__ void __launch_bounds__(256, 1)
flash_mma(const float* __restrict__ qkv, float* __restrict__ att) {
    extern __shared__ float sm[];
    float* Qhi = sm;                     // [128][FD]
    float* Qlo = Qhi + 128 * FD;         // [128][FD]
    float* Khi = Qlo + 128 * FD;         // [64][FD]
    float* Klo = Khi + 64 * FD;          // [64][FD]
    float* Vt  = Klo + 64 * FD;          // [64][FD]  (Vt[d][kv])
    float* Ps  = Vt + 64 * FD;           // [128][FD]

    const int tid = threadIdx.x;
    const int wid = tid >> 5, lane = tid & 31;
    const int r = lane >> 2, cl = lane & 3;
    const int qb = blockIdx.x << 7;
    const int bh = blockIdx.y;
    const int b = bh / NHEAD, h = bh % NHEAD;
    const float* qptr = qkv + (size_t)b * SEQ * QKVC + h * HDIM;
    const float* kptr = qptr + CDIM;
    const float* vptr = qptr + 2 * CDIM;

    {
        int row = tid >> 1;
        const float* src = qptr + (size_t)(qb + row) * QKVC;
#pragma unroll
        for (int e = 0; e < 8; e++) {
            int c4 = ((tid & 1) << 3) + e;
            float4 v = *(const float4*)(src + (c4 << 2));
            v.x *= 8.f; v.y *= 8.f; v.z *= 8.f; v.w *= 8.f;
            float4 hi, lo;
            hi.x = cvt_tf32(v.x); lo.x = v.x - hi.x;
            hi.y = cvt_tf32(v.y); lo.y = v.y - hi.y;
            hi.z = cvt_tf32(v.z); lo.z = v.z - hi.z;
            hi.w = cvt_tf32(v.w); lo.w = v.w - hi.w;
            *(float4*)&Qhi[row * FD + (c4 << 2)] = hi;
            *(float4*)&Qlo[row * FD + (c4 << 2)] = lo;
        }
    }

    float mi0 = -3.4e38f, mi1 = -3.4e38f, li0 = 0.f, li1 = 0.f;
    float o[8][4];
#pragma unroll
    for (int j = 0; j < 8; j++)
#pragma unroll
        for (int e = 0; e < 4; e++) o[j][e] = 0.f;

    const int m0 = wid << 4;

    for (int t = 0; t < 16; t++) {
        __syncthreads();
        {
            int row = tid >> 2;
            const float* ksrc = kptr + (size_t)((t << 6) + row) * QKVC;
            const float* vsrc = vptr + (size_t)((t << 6) + row) * QKVC;
#pragma unroll
            for (int e = 0; e < 4; e++) {
                int c4 = (tid & 3) + (e << 2);
                float4 v = *(const float4*)(ksrc + (c4 << 2));
                float4 hi, lo;
                hi.x = cvt_tf32(v.x); lo.x = v.x - hi.x;
                hi.y = cvt_tf32(v.y); lo.y = v.y - hi.y;
                hi.z = cvt_tf32(v.z); lo.z = v.z - hi.z;
                hi.w = cvt_tf32(v.w); lo.w = v.w - hi.w;
                *(float4*)&Khi[row * FD + (c4 << 2)] = hi;
                *(float4*)&Klo[row * FD + (c4 << 2)] = lo;
                float4 vv = *(const float4*)(vsrc + (c4 << 2));
                int dc = c4 << 2;
                Vt[(dc + 0) * FD + row] = vv.x;
                Vt[(dc + 1) * FD + row] = vv.y;
                Vt[(dc + 2) * FD + row] = vv.z;
                Vt[(dc + 3) * FD + row] = vv.w;
            }
        }
        __syncthreads();

        float s[8][4];
#pragma unroll
        for (int j = 0; j < 8; j++)
#pragma unroll
            for (int e = 0; e < 4; e++) s[j][e] = 0.f;

#pragma unroll
        for (int ks = 0; ks < 8; ks++) {
            int k0 = ks << 3;
            uint32_t ah[4], al[4];
            ah[0] = __float_as_uint(Qhi[(m0 + r) * FD + k0 + cl]);
            ah[1] = __float_as_uint(Qhi[(m0 + r + 8) * FD + k0 + cl]);
            ah[2] = __float_as_uint(Qhi[(m0 + r) * FD + k0 + cl + 4]);
            ah[3] = __float_as_uint(Qhi[(m0 + r + 8) * FD + k0 + cl + 4]);
            al[0] = __float_as_uint(Qlo[(m0 + r) * FD + k0 + cl]);
            al[1] = __float_as_uint(Qlo[(m0 + r + 8) * FD + k0 + cl]);
            al[2] = __float_as_uint(Qlo[(m0 + r) * FD + k0 + cl + 4]);
            al[3] = __float_as_uint(Qlo[(m0 + r + 8) * FD + k0 + cl + 4]);
#pragma unroll
            for (int j = 0; j < 8; j++) {
                int nr = (j << 3) + r;
                uint32_t bh2[2], bl2[2];
                bh2[0] = __float_as_uint(Khi[nr * FD + k0 + cl]);
                bh2[1] = __float_as_uint(Khi[nr * FD + k0 + cl + 4]);
                bl2[0] = __float_as_uint(Klo[nr * FD + k0 + cl]);
                bl2[1] = __float_as_uint(Klo[nr * FD + k0 + cl + 4]);
                mma_tf32(s[j], ah, bh2);
                mma_tf32(s[j], al, bh2);
                mma_tf32(s[j], ah, bl2);
            }
        }

        float mx0 = s[0][0], mx1 = s[0][2];
#pragma unroll
        for (int j = 0; j < 8; j++) {
            mx0 = fmaxf(mx0, fmaxf(s[j][0], s[j][1]));
            mx1 = fmaxf(mx1, fmaxf(s[j][2], s[j][3]));
        }
        mx0 = fmaxf(mx0, __shfl_xor_sync(0xffffffffu, mx0, 1));
        mx0 = fmaxf(mx0, __shfl_xor_sync(0xffffffffu, mx0, 2));
        mx1 = fmaxf(mx1, __shfl_xor_sync(0xffffffffu, mx1, 1));
        mx1 = fmaxf(mx1, __shfl_xor_sync(0xffffffffu, mx1, 2));
        float mn0 = fmaxf(mi0, mx0), mn1 = fmaxf(mi1, mx1);
        float sc0 = __expf(mi0 - mn0), sc1 = __expf(mi1 - mn1);
        mi0 = mn0; mi1 = mn1;
        float sum0 = 0.f, sum1 = 0.f;
#pragma unroll
        for (int j = 0; j < 8; j++) {
            s[j][0] = __expf(s[j][0] - mn0);
            s[j][1] = __expf(s[j][1] - mn0);
            s[j][2] = __expf(s[j][2] - mn1);
            s[j][3] = __expf(s[j][3] - mn1);
            sum0 += s[j][0] + s[j][1];
            sum1 += s[j][2] + s[j][3];
        }
        sum0 += __shfl_xor_sync(0xffffffffu, sum0, 1);
        sum0 += __shfl_xor_sync(0xffffffffu, sum0, 2);
        sum1 += __shfl_xor_sync(0xffffffffu, sum1, 1);
        sum1 += __shfl_xor_sync(0xffffffffu, sum1, 2);
        li0 = li0 * sc0 + sum0;
        li1 = li1 * sc1 + sum1;
#pragma unroll
        for (int j = 0; j < 8; j++) {
            o[j][0] *= sc0; o[j][1] *= sc0;
            o[j][2] *= sc1; o[j][3] *= sc1;
        }

#pragma unroll
        for (int j = 0; j < 8; j++) {
            *(float2*)&Ps[(m0 + r) * FD + (j << 3) + (cl << 1)] =
                make_float2(s[j][0], s[j][1]);
            *(float2*)&Ps[(m0 + r + 8) * FD + (j << 3) + (cl << 1)] =
                make_float2(s[j][2], s[j][3]);
        }
        __syncwarp();

#pragma unroll
        for (int ks = 0; ks < 8; ks++) {
            int k0 = ks << 3;
            uint32_t a[4];
            a[0] = __float_as_uint(Ps[(m0 + r) * FD + k0 + cl]);
            a[1] = __float_as_uint(Ps[(m0 + r + 8) * FD + k0 + cl]);
            a[2] = __float_as_uint(Ps[(m0 + r) * FD + k0 + cl + 4]);
            a[3] = __float_as_uint(Ps[(m0 + r + 8) * FD + k0 + cl + 4]);
#pragma unroll
            for (int j = 0; j < 8; j++) {
                uint32_t b2[2];
                b2[0] = __float_as_uint(Vt[((j << 3) + r) * FD + k0 + cl]);
                b2[1] = __float_as_uint(Vt[((j << 3) + r) * FD + k0 + cl + 4]);
                mma_tf32(o[j], a, b2);
            }
        }
    }

    {
        float inv0 = 1.f / li0, inv1 = 1.f / li1;
        float* o0 = att + ((size_t)(b * SEQ + qb + m0 + r)) * CDIM + h * HDIM;
        float* o1 = o0 + 8 * CDIM;
#pragma unroll
        for (int j = 0; j < 8; j++) {
            int col = (j << 3) + (cl << 1);
            *(float2*)&o0[col] = make_float2(o[j][0] * inv0, o[j][1] * inv0);
            *(float2*)&o1[col] = make_float2(o[j][2] * inv1, o[j][3] * inv1);
        }
    }
}
#define FLASH_SMEM ((128 + 128 + 64 + 64 + 64 + 128) * FD * 4)

// ---------------- launch --------------------------------------------------
extern "C" void kernel_launch(void* const* d_in, const int* in_sizes, int n_in,
                              void* d_out, int out_size) {
    const float* x     = (const float*)d_in[0];
    const float* ln1w  = (const float*)d_in[1];
    const float* ln1b  = (const float*)d_in[2];
    const float* ln2w  = (const float*)d_in[3];
    const float* ln2b  = (const float*)d_in[4];
    const float* wqkv  = (const float*)d_in[5];
    const float* wproj = (const float*)d_in[6];
    const float* wfc1  = (const float*)d_in[7];
    const float* bfc1  = (const float*)d_in[8];
    const float* wfc2  = (const float*)d_in[9];
    const float* bfc2  = (const float*)d_in[10];
    float* out = (float*)d_out;

    float *p_h, *p_qkv, *p_att, *p_x1, *p_fc1;
    float *p_wqkv_t, *p_wproj_t, *p_wfc1_t, *p_wfc2_t;
    cudaGetSymbolAddress((void**)&p_h, g_h);
    cudaGetSymbolAddress((void**)&p_qkv, g_qkv);
    cudaGetSymbolAddress((void**)&p_att, g_att);
    cudaGetSymbolAddress((void**)&p_x1, g_x1);
    cudaGetSymbolAddress((void**)&p_fc1, g_fc1);
    cudaGetSymbolAddress((void**)&p_wqkv_t, g_wqkv_t);
    cudaGetSymbolAddress((void**)&p_wproj_t, g_wproj_t);
    cudaGetSymbolAddress((void**)&p_wfc1_t, g_wfc1_t);
    cudaGetSymbolAddress((void**)&p_wfc2_t, g_wfc2_t);

    cudaFuncSetAttribute(flash_mma, cudaFuncAttributeMaxDynamicSharedMemorySize,
                         FLASH_SMEM);
    cudaFuncSetAttribute(gemm_mma, cudaFuncAttributeMaxDynamicSharedMemorySize,
                         GEMM_SMEM);

    dim3 tb(32, 8);
    transpose_kernel<<<dim3(QKVC / 32, CDIM / 32), tb>>>(wqkv, p_wqkv_t, CDIM, QKVC);
    transpose_kernel<<<dim3(CDIM / 32, CDIM / 32), tb>>>(wproj, p_wproj_t, CDIM, CDIM);
    transpose_kernel<<<dim3(HID / 32, CDIM / 32), tb>>>(wfc1, p_wfc1_t, CDIM, HID);
    transpose_kernel<<<dim3(CDIM / 32, HID / 32), tb>>>(wfc2, p_wfc2_t, HID, CDIM);

    // 1) h = LN1(x)
    ln_kernel<<<TOKS, 256>>>(x, ln1w, ln1b, p_h);
    // 2) qkv = h @ w_qkv
    gemm_mma<<<dim3(QKVC / 128, TOKS / 128), 256, GEMM_SMEM>>>(
        p_h, p_wqkv_t, p_qkv, QKVC, CDIM, nullptr, nullptr, 0);
    // 3-5) fused attention (tensor cores)
    flash_mma<<<dim3(SEQ / 128, NBH), 256, FLASH_SMEM>>>(p_qkv, p_att);
    // 6) x1 = x + att @ w_proj
    gemm_mma<<<dim3(CDIM / 128, TOKS / 128), 256, GEMM_SMEM>>>(
        p_att, p_wproj_t, p_x1, CDIM, CDIM, nullptr, x, 0);
    // 7) h = LN2(x1)
    ln_kernel<<<TOKS, 256>>>(p_x1, ln2w, ln2b, p_h);
    // 8) fc1 = gelu(h @ w_fc1 + b_fc1)
    gemm_mma<<<dim3(HID / 128, TOKS / 128), 256, GEMM_SMEM>>>(
        p_h, p_wfc1_t, p_fc1, HID, CDIM, bfc1, nullptr, 1);
    // 9) out = x1 + fc1 @ w_fc2 + b_fc2
    gemm_mma<<<dim3(CDIM / 128, TOKS / 128), 256, GEMM_SMEM>>>(
        p_fc1, p_wfc2_t, out, CDIM, HID, bfc2, p_x1, 0);
}